// round 2
// baseline (speedup 1.0000x reference)
#include <cuda_runtime.h>
#include <math.h>

// Problem constants (shapes fixed by the dataset)
#define N_   100000
#define E_   800000
#define ET_  900000      // E + N self loops
#define HID_ 128
#define H_   4
#define C_   32
#define L_   3
#define OUT_ 5
#define NEG_SLOPE 0.2f

// ---------------- scratch (static device globals; no allocation) -------------
__device__ __align__(16) float  g_h   [N_ * HID_];   // current node features
__device__ __align__(16) float  g_xh  [N_ * HID_];   // xh = h @ Wg[l]
__device__ __align__(16) float  g_g   [N_ * HID_];   // aggregation target / g
__device__ __align__(16) float  g_als [N_ * H_];
__device__ __align__(16) float  g_ald [N_ * H_];
__device__ __align__(16) float  g_m   [N_ * H_];     // segment max
__device__ __align__(16) float  g_den [N_ * H_];     // segment sum of exp
__device__ __align__(16) float  g_deg [N_];
__device__ __align__(16) float  g_loop[N_];          // self-loop attr (mean of incoming)
__device__ __align__(16) float  g_wec [L_ * H_];     // a_edge . We per (l,h)
__device__ __align__(16) double g_red [2];           // sum, sumsq for layernorm
__device__ __align__(16) float  g_stats[2];          // mean, inv_std

// ---------------- helpers ----------------------------------------------------
__device__ __forceinline__ float atomicMaxFloat(float* addr, float value) {
    if (value >= 0.0f)
        return __int_as_float(atomicMax((int*)addr, __float_as_int(value)));
    else
        return __uint_as_float(atomicMin((unsigned int*)addr, __float_as_uint(value)));
}

__device__ __forceinline__ float lrelu(float x) {
    return x > 0.0f ? x : NEG_SLOPE * x;
}

// ---------------- self-loop attr (fill_value='mean') -------------------------
__global__ void k_zero_deg() {
    int i = blockIdx.x * blockDim.x + threadIdx.x;
    if (i < N_) { g_deg[i] = 0.0f; g_loop[i] = 0.0f; }
}

__global__ void k_selfloop1(const int* __restrict__ ei,
                            const float* __restrict__ ea) {
    int e = blockIdx.x * blockDim.x + threadIdx.x;
    if (e < E_) {
        int d = ei[E_ + e];
        atomicAdd(&g_deg[d], 1.0f);
        atomicAdd(&g_loop[d], ea[e]);
    }
}

__global__ void k_selfloop2() {
    int i = blockIdx.x * blockDim.x + threadIdx.x;
    if (i < N_) g_loop[i] = g_loop[i] / fmaxf(g_deg[i], 1.0f);
}

// ---------------- input projection h = x @ Win + b_in ------------------------
__global__ void k_ingemm(const float* __restrict__ x,
                         const float* __restrict__ Win,
                         const float* __restrict__ bin) {
    __shared__ float xs[32];
    int n = blockIdx.x;
    int j = threadIdx.x;                  // 0..127
    if (j < 32) xs[j] = x[n * 32 + j];
    __syncthreads();
    float acc = bin[j];
#pragma unroll
    for (int k = 0; k < 32; k++) acc += xs[k] * Win[k * HID_ + j];
    g_h[n * HID_ + j] = acc;
}

// ---------------- tiled GEMM: g_xh = g_h @ B (128x128) -----------------------
// block: 256 threads, tile 64 rows x 128 cols, K chunks of 32
__global__ void k_gemm(const float* __restrict__ B) {
    __shared__ float As[64][33];
    __shared__ float Bs[32][128];
    const int tx = threadIdx.x & 15;      // 0..15 (col group)
    const int ty = threadIdx.x >> 4;      // 0..15 (row group)
    const int row0 = blockIdx.x * 64;

    float acc[4][8];
#pragma unroll
    for (int i = 0; i < 4; i++)
#pragma unroll
        for (int j = 0; j < 8; j++) acc[i][j] = 0.0f;

    for (int kc = 0; kc < 4; kc++) {
        const int k0 = kc * 32;
        // load A tile (64x32)
        {
            int kk = threadIdx.x & 31;
            int rb = threadIdx.x >> 5;   // 0..7
#pragma unroll
            for (int i = 0; i < 8; i++) {
                int r = rb + i * 8;
                int gr = row0 + r;
                As[r][kk] = (gr < N_) ? g_h[gr * HID_ + k0 + kk] : 0.0f;
            }
        }
        // load B tile (32x128)
        {
            int col = threadIdx.x & 127;
            int kb  = threadIdx.x >> 7;  // 0..1
#pragma unroll
            for (int i = 0; i < 16; i++) {
                int kk = kb + i * 2;
                Bs[kk][col] = B[(k0 + kk) * HID_ + col];
            }
        }
        __syncthreads();
#pragma unroll
        for (int k = 0; k < 32; k++) {
            float a[4], b[8];
#pragma unroll
            for (int i = 0; i < 4; i++) a[i] = As[ty + i * 16][k];
#pragma unroll
            for (int j = 0; j < 8; j++) b[j] = Bs[k][tx + j * 16];
#pragma unroll
            for (int i = 0; i < 4; i++)
#pragma unroll
                for (int j = 0; j < 8; j++) acc[i][j] += a[i] * b[j];
        }
        __syncthreads();
    }
#pragma unroll
    for (int i = 0; i < 4; i++) {
        int gr = row0 + ty + i * 16;
        if (gr < N_) {
#pragma unroll
            for (int j = 0; j < 8; j++)
                g_xh[gr * HID_ + tx + j * 16] = acc[i][j];
        }
    }
}

// ---------------- per-node attention coefficients ----------------------------
__global__ void k_attn(const float* __restrict__ a_src,
                       const float* __restrict__ a_dst) {
    int t = blockIdx.x * blockDim.x + threadIdx.x;
    if (t >= N_ * H_) return;
    int n = t >> 2, h = t & 3;
    const float4* xr  = (const float4*)(g_xh + n * HID_ + h * C_);
    const float4* as4 = (const float4*)(a_src + h * C_);
    const float4* ad4 = (const float4*)(a_dst + h * C_);
    float s = 0.0f, d = 0.0f;
#pragma unroll
    for (int i = 0; i < 8; i++) {
        float4 xv = xr[i], av = as4[i], dv = ad4[i];
        s += xv.x * av.x + xv.y * av.y + xv.z * av.z + xv.w * av.w;
        d += xv.x * dv.x + xv.y * dv.y + xv.z * dv.z + xv.w * dv.w;
    }
    g_als[t] = s;
    g_ald[t] = d;
}

// ---------------- edge-attr attention scalars (12 of them) -------------------
__global__ void k_wec(const float* __restrict__ We,
                      const float* __restrict__ a_edge) {
    int t = threadIdx.x;
    if (t >= L_ * H_) return;
    int l = t / H_, h = t % H_;
    float s = 0.0f;
    for (int c = 0; c < C_; c++)
        s += We[l * HID_ + h * C_ + c] * a_edge[l * HID_ + h * C_ + c];
    g_wec[t] = s;
}

// ---------------- per-layer init --------------------------------------------
__global__ void k_init() {
    int i = blockIdx.x * blockDim.x + threadIdx.x;
    if (i < N_ * HID_) g_g[i] = 0.0f;
    if (i < N_ * H_) { g_den[i] = 0.0f; g_m[i] = -INFINITY; }
    if (i < 2) g_red[i] = 0.0;
}

// ---------------- edge pass 1: segment max of logits -------------------------
__global__ void k_emax(const int* __restrict__ ei,
                       const float* __restrict__ ea, int l) {
    int t = blockIdx.x * blockDim.x + threadIdx.x;
    if (t >= ET_ * H_) return;
    int e = t >> 2, h = t & 3;
    int s, d; float av;
    if (e < E_) {
        s = ei[e]; d = ei[E_ + e]; av = ea[e];
    } else {
        s = d = e - E_; av = g_loop[s];
    }
    float lg = g_als[s * H_ + h] + g_ald[d * H_ + h] + av * g_wec[l * H_ + h];
    lg = lrelu(lg);
    atomicMaxFloat(&g_m[d * H_ + h], lg);
}

// ---------------- edge pass 2: exp + weighted scatter (warp per edge) --------
__global__ void k_eagg(const int* __restrict__ ei,
                       const float* __restrict__ ea, int l) {
    int gt = blockIdx.x * blockDim.x + threadIdx.x;
    int e = gt >> 5;
    int lane = gt & 31;
    if (e >= ET_) return;
    int s = 0, d = 0; float av = 0.0f;
    if (lane == 0) {
        if (e < E_) {
            s = ei[e]; d = ei[E_ + e]; av = ea[e];
        } else {
            s = d = e - E_; av = g_loop[s];
        }
    }
    s  = __shfl_sync(0xffffffffu, s, 0);
    d  = __shfl_sync(0xffffffffu, d, 0);
    av = __shfl_sync(0xffffffffu, av, 0);

    int h = lane >> 3;                      // 8 lanes per head
    float lg = g_als[s * H_ + h] + g_ald[d * H_ + h] + av * g_wec[l * H_ + h];
    lg = lrelu(lg);
    float ex = __expf(lg - g_m[d * H_ + h]);
    if ((lane & 7) == 0) atomicAdd(&g_den[d * H_ + h], ex);

    float4 xv = ((const float4*)g_xh)[s * 32 + lane];
    float* op = g_g + d * HID_ + lane * 4;
    atomicAdd(op + 0, ex * xv.x);
    atomicAdd(op + 1, ex * xv.y);
    atomicAdd(op + 2, ex * xv.z);
    atomicAdd(op + 3, ex * xv.w);
}

// ---------------- normalize by den, add bias, reduce sum/sumsq ---------------
__global__ void k_norm_red(const float* __restrict__ bg) {
    float s1 = 0.0f, s2 = 0.0f;
    const int total = N_ * 32;              // float4 groups
    for (int idx = blockIdx.x * blockDim.x + threadIdx.x; idx < total;
         idx += gridDim.x * blockDim.x) {
        int n = idx >> 5, q = idx & 31;
        float den = g_den[n * H_ + (q >> 3)] + 1e-16f;
        float inv = 1.0f / den;
        float4 v = ((float4*)g_g)[idx];
        float4 b = ((const float4*)bg)[q];
        v.x = v.x * inv + b.x;
        v.y = v.y * inv + b.y;
        v.z = v.z * inv + b.z;
        v.w = v.w * inv + b.w;
        ((float4*)g_g)[idx] = v;
        s1 += v.x + v.y + v.z + v.w;
        s2 += v.x * v.x + v.y * v.y + v.z * v.z + v.w * v.w;
    }
    __shared__ float r1[256], r2[256];
    int tid = threadIdx.x;
    r1[tid] = s1; r2[tid] = s2;
    __syncthreads();
    for (int off = 128; off > 0; off >>= 1) {
        if (tid < off) { r1[tid] += r1[tid + off]; r2[tid] += r2[tid + off]; }
        __syncthreads();
    }
    if (tid == 0) {
        atomicAdd(&g_red[0], (double)r1[0]);
        atomicAdd(&g_red[1], (double)r2[0]);
    }
}

__global__ void k_stats() {
    double M = (double)N_ * (double)HID_;
    double mean = g_red[0] / M;
    double var  = g_red[1] / M - mean * mean;
    g_stats[0] = (float)mean;
    g_stats[1] = (float)(1.0 / sqrt(var + 1e-5));
}

// ---------------- apply LN + residual ReLU -----------------------------------
__global__ void k_apply(const float* __restrict__ lnw,
                        const float* __restrict__ lnb) {
    int idx = blockIdx.x * blockDim.x + threadIdx.x;
    if (idx >= N_ * 32) return;
    int q = idx & 31;
    float mean = g_stats[0], istd = g_stats[1];
    float4 g = ((float4*)g_g)[idx];
    float4 h = ((float4*)g_h)[idx];
    float4 w = ((const float4*)lnw)[q];
    float4 b = ((const float4*)lnb)[q];
    float4 o;
    o.x = fmaxf((g.x - mean) * istd * w.x + b.x + h.x, 0.0f);
    o.y = fmaxf((g.y - mean) * istd * w.y + b.y + h.y, 0.0f);
    o.z = fmaxf((g.z - mean) * istd * w.z + b.z + h.z, 0.0f);
    o.w = fmaxf((g.w - mean) * istd * w.w + b.w + h.w, 0.0f);
    ((float4*)g_h)[idx] = o;
}

// ---------------- output projection ------------------------------------------
__global__ void k_out(const float* __restrict__ Wout,
                      const float* __restrict__ bout,
                      float* __restrict__ out) {
    __shared__ float ws[HID_ * OUT_];
    __shared__ float bs[OUT_];
    for (int i = threadIdx.x; i < HID_ * OUT_; i += blockDim.x) ws[i] = Wout[i];
    if (threadIdx.x < OUT_) bs[threadIdx.x] = bout[threadIdx.x];
    __syncthreads();
    int n = blockIdx.x * blockDim.x + threadIdx.x;
    if (n >= N_) return;
    float acc[OUT_];
#pragma unroll
    for (int j = 0; j < OUT_; j++) acc[j] = bs[j];
    const float4* hr = (const float4*)(g_h + n * HID_);
#pragma unroll 8
    for (int k4 = 0; k4 < 32; k4++) {
        float4 hv = hr[k4];
        float hvv[4] = {hv.x, hv.y, hv.z, hv.w};
#pragma unroll
        for (int t = 0; t < 4; t++) {
            int k = k4 * 4 + t;
#pragma unroll
            for (int j = 0; j < OUT_; j++) acc[j] += hvv[t] * ws[k * OUT_ + j];
        }
    }
#pragma unroll
    for (int j = 0; j < OUT_; j++) out[n * OUT_ + j] = acc[j];
}

// ---------------- launch ------------------------------------------------------
extern "C" void kernel_launch(void* const* d_in, const int* in_sizes, int n_in,
                              void* d_out, int out_size) {
    const float* x      = (const float*)d_in[0];
    const int*   ei     = (const int*)d_in[1];   // int32! (JAX x64 disabled)
    const float* ea     = (const float*)d_in[2];
    const float* Win    = (const float*)d_in[3];
    const float* b_in   = (const float*)d_in[4];
    const float* Wg     = (const float*)d_in[5];
    const float* bg     = (const float*)d_in[6];
    const float* a_src  = (const float*)d_in[7];
    const float* a_dst  = (const float*)d_in[8];
    const float* We     = (const float*)d_in[9];
    const float* a_edge = (const float*)d_in[10];
    const float* ln_w   = (const float*)d_in[11];
    const float* ln_b   = (const float*)d_in[12];
    const float* Wout   = (const float*)d_in[13];
    const float* bout   = (const float*)d_in[14];
    float*       out    = (float*)d_out;

    k_zero_deg <<<(N_ + 255) / 256, 256>>>();
    k_selfloop1<<<(E_ + 255) / 256, 256>>>(ei, ea);
    k_selfloop2<<<(N_ + 255) / 256, 256>>>();
    k_ingemm   <<<N_, 128>>>(x, Win, b_in);
    k_wec      <<<1, 32>>>(We, a_edge);

    for (int l = 0; l < L_; l++) {
        k_gemm    <<<(N_ + 63) / 64, 256>>>(Wg + l * HID_ * HID_);
        k_attn    <<<(N_ * H_ + 255) / 256, 256>>>(a_src + l * H_ * C_,
                                                   a_dst + l * H_ * C_);
        k_init    <<<(N_ * HID_ + 255) / 256, 256>>>();
        k_emax    <<<(ET_ * H_ + 255) / 256, 256>>>(ei, ea, l);
        k_eagg    <<<(ET_ * 32 + 255) / 256, 256>>>(ei, ea, l);
        k_norm_red<<<1184, 256>>>(bg + l * HID_);
        k_stats   <<<1, 1>>>();
        k_apply   <<<(N_ * 32 + 255) / 256, 256>>>(ln_w + l * HID_,
                                                   ln_b + l * HID_);
    }
    k_out<<<(N_ + 255) / 256, 256>>>(Wout, bout, out);
}

// round 3
// speedup vs baseline: 1.9769x; 1.9769x over previous
#include <cuda_runtime.h>
#include <math.h>

// Problem constants (shapes fixed by the dataset)
#define N_   100000
#define E_   800000
#define ET_  900000      // E + N self loops
#define HID_ 128
#define H_   4
#define C_   32
#define L_   3
#define OUT_ 5
#define NEG_SLOPE 0.2f
#define NBSCAN 98        // ceil(N_/1024)

// ---------------- scratch (static device globals; no allocation) -------------
__device__ __align__(16) float  g_h   [N_ * HID_];   // current node features
__device__ __align__(16) float  g_xh  [N_ * HID_];   // xh = h @ Wg[l]
__device__ __align__(16) float  g_g   [N_ * HID_];   // post-aggregation g
__device__ __align__(16) float  g_als [N_ * H_];
__device__ __align__(16) float  g_ald [N_ * H_];
__device__ __align__(16) float  g_loop[N_];          // self-loop attr
__device__ __align__(16) float  g_wec [L_ * H_];     // a_edge . We per (l,h)
__device__ __align__(16) double g_red [2];           // sum, sumsq for layernorm
__device__ __align__(16) float  g_stats[2];          // mean, inv_std
// CSR
__device__ __align__(16) int    g_cnt [N_];
__device__ __align__(16) int    g_row [N_ + 1];
__device__ __align__(16) int    g_fill[N_];
__device__ __align__(16) int    g_bsum[NBSCAN];
__device__ __align__(16) int    g_bsumx[128];
__device__ __align__(16) int2   g_se  [ET_];         // (src, edge_attr bits) dst-sorted

// ---------------- CSR build ---------------------------------------------------
__global__ void k_cnt_init() {
    int i = blockIdx.x * blockDim.x + threadIdx.x;
    if (i < N_) { g_cnt[i] = 1; g_loop[i] = 0.0f; }   // 1 = self loop
}

__global__ void k_hist(const int* __restrict__ ei, const float* __restrict__ ea) {
    int e = blockIdx.x * blockDim.x + threadIdx.x;
    if (e < E_) {
        int d = ei[E_ + e];
        atomicAdd(&g_cnt[d], 1);
        atomicAdd(&g_loop[d], ea[e]);
    }
}

__global__ void k_scan1() {
    __shared__ int wtot[32];
    int i = blockIdx.x * 1024 + threadIdx.x;
    int lane = threadIdx.x & 31, wid = threadIdx.x >> 5;
    int v = (i < N_) ? g_cnt[i] : 0;
    int inc = v;
#pragma unroll
    for (int o = 1; o < 32; o <<= 1) {
        int t = __shfl_up_sync(0xffffffffu, inc, o);
        if (lane >= o) inc += t;
    }
    if (lane == 31) wtot[wid] = inc;
    __syncthreads();
    if (wid == 0) {
        int w = wtot[lane];
        int winc = w;
#pragma unroll
        for (int o = 1; o < 32; o <<= 1) {
            int t = __shfl_up_sync(0xffffffffu, winc, o);
            if (lane >= o) winc += t;
        }
        wtot[lane] = winc - w;          // exclusive warp offsets
    }
    __syncthreads();
    int excl = inc - v + wtot[wid];
    if (i < N_) g_row[i] = excl;        // block-local exclusive
    if (threadIdx.x == 1023) g_bsum[blockIdx.x] = excl + v;
}

__global__ void k_scan2() {
    __shared__ int sh[128];
    int t = threadIdx.x;
    int v = (t < NBSCAN) ? g_bsum[t] : 0;
    sh[t] = v;
    __syncthreads();
    for (int o = 1; o < 128; o <<= 1) {
        int x = (t >= o) ? sh[t - o] : 0;
        __syncthreads();
        sh[t] += x;
        __syncthreads();
    }
    g_bsumx[t] = sh[t] - v;             // exclusive
}

__global__ void k_scan3() {
    int i = blockIdx.x * blockDim.x + threadIdx.x;
    if (i < N_) g_row[i] += g_bsumx[i >> 10];
    if (i == 0) g_row[N_] = ET_;
}

__global__ void k_selfloop_fin() {      // loop attr = mean of incoming
    int i = blockIdx.x * blockDim.x + threadIdx.x;
    if (i < N_) g_loop[i] = g_loop[i] / fmaxf((float)(g_cnt[i] - 1), 1.0f);
}

__global__ void k_scatter_self() {
    int i = blockIdx.x * blockDim.x + threadIdx.x;
    if (i < N_) {
        g_fill[i] = 1;
        int2 se; se.x = i; se.y = __float_as_int(g_loop[i]);
        g_se[g_row[i]] = se;
    }
}

__global__ void k_scatter_edges(const int* __restrict__ ei,
                                const float* __restrict__ ea) {
    int e = blockIdx.x * blockDim.x + threadIdx.x;
    if (e < E_) {
        int d = ei[E_ + e];
        int pos = g_row[d] + atomicAdd(&g_fill[d], 1);
        int2 se; se.x = ei[e]; se.y = __float_as_int(ea[e]);
        g_se[pos] = se;
    }
}

// ---------------- input projection: h = x @ Win + b_in (tiled) ----------------
__global__ void k_ingemm(const float* __restrict__ x,
                         const float* __restrict__ Win,
                         const float* __restrict__ bin) {
    __shared__ float As[64][33];
    __shared__ float Bs[32][128];
    const int tx = threadIdx.x & 15;
    const int ty = threadIdx.x >> 4;
    const int row0 = blockIdx.x * 64;

    // load A tile (64x32) from x
    {
        int kk = threadIdx.x & 31;
        int rb = threadIdx.x >> 5;
#pragma unroll
        for (int i = 0; i < 8; i++) {
            int r = rb + i * 8;
            int gr = row0 + r;
            As[r][kk] = (gr < N_) ? x[gr * 32 + kk] : 0.0f;
        }
    }
    // load B (32x128) = Win
    {
        int col = threadIdx.x & 127;
        int kb  = threadIdx.x >> 7;
#pragma unroll
        for (int i = 0; i < 16; i++) {
            int kk = kb + i * 2;
            Bs[kk][col] = Win[kk * HID_ + col];
        }
    }
    __syncthreads();

    float acc[4][8];
#pragma unroll
    for (int i = 0; i < 4; i++)
#pragma unroll
        for (int j = 0; j < 8; j++) acc[i][j] = 0.0f;
#pragma unroll
    for (int k = 0; k < 32; k++) {
        float a[4], b[8];
#pragma unroll
        for (int i = 0; i < 4; i++) a[i] = As[ty + i * 16][k];
#pragma unroll
        for (int j = 0; j < 8; j++) b[j] = Bs[k][tx + j * 16];
#pragma unroll
        for (int i = 0; i < 4; i++)
#pragma unroll
            for (int j = 0; j < 8; j++) acc[i][j] += a[i] * b[j];
    }
#pragma unroll
    for (int i = 0; i < 4; i++) {
        int gr = row0 + ty + i * 16;
        if (gr < N_) {
#pragma unroll
            for (int j = 0; j < 8; j++)
                g_h[gr * HID_ + tx + j * 16] = acc[i][j] + bin[tx + j * 16];
        }
    }
}

// ---------------- tiled GEMM: g_xh = g_h @ B (128x128) -----------------------
__global__ void k_gemm(const float* __restrict__ B) {
    __shared__ float As[64][33];
    __shared__ float Bs[32][128];
    const int tx = threadIdx.x & 15;
    const int ty = threadIdx.x >> 4;
    const int row0 = blockIdx.x * 64;

    float acc[4][8];
#pragma unroll
    for (int i = 0; i < 4; i++)
#pragma unroll
        for (int j = 0; j < 8; j++) acc[i][j] = 0.0f;

    for (int kc = 0; kc < 4; kc++) {
        const int k0 = kc * 32;
        {
            int kk = threadIdx.x & 31;
            int rb = threadIdx.x >> 5;
#pragma unroll
            for (int i = 0; i < 8; i++) {
                int r = rb + i * 8;
                int gr = row0 + r;
                As[r][kk] = (gr < N_) ? g_h[gr * HID_ + k0 + kk] : 0.0f;
            }
        }
        {
            int col = threadIdx.x & 127;
            int kb  = threadIdx.x >> 7;
#pragma unroll
            for (int i = 0; i < 16; i++) {
                int kk = kb + i * 2;
                Bs[kk][col] = B[(k0 + kk) * HID_ + col];
            }
        }
        __syncthreads();
#pragma unroll
        for (int k = 0; k < 32; k++) {
            float a[4], b[8];
#pragma unroll
            for (int i = 0; i < 4; i++) a[i] = As[ty + i * 16][k];
#pragma unroll
            for (int j = 0; j < 8; j++) b[j] = Bs[k][tx + j * 16];
#pragma unroll
            for (int i = 0; i < 4; i++)
#pragma unroll
                for (int j = 0; j < 8; j++) acc[i][j] += a[i] * b[j];
        }
        __syncthreads();
    }
#pragma unroll
    for (int i = 0; i < 4; i++) {
        int gr = row0 + ty + i * 16;
        if (gr < N_) {
#pragma unroll
            for (int j = 0; j < 8; j++)
                g_xh[gr * HID_ + tx + j * 16] = acc[i][j];
        }
    }
}

// ---------------- per-node attention coefficients (+ g_red reset) -------------
__global__ void k_attn(const float* __restrict__ a_src,
                       const float* __restrict__ a_dst) {
    int t = blockIdx.x * blockDim.x + threadIdx.x;
    if (t == 0) { g_red[0] = 0.0; g_red[1] = 0.0; }
    if (t >= N_ * H_) return;
    int n = t >> 2, h = t & 3;
    const float4* xr  = (const float4*)(g_xh + n * HID_ + h * C_);
    const float4* as4 = (const float4*)(a_src + h * C_);
    const float4* ad4 = (const float4*)(a_dst + h * C_);
    float s = 0.0f, d = 0.0f;
#pragma unroll
    for (int i = 0; i < 8; i++) {
        float4 xv = xr[i], av = as4[i], dv = ad4[i];
        s += xv.x * av.x + xv.y * av.y + xv.z * av.z + xv.w * av.w;
        d += xv.x * dv.x + xv.y * dv.y + xv.z * dv.z + xv.w * dv.w;
    }
    g_als[t] = s;
    g_ald[t] = d;
}

// ---------------- edge-attr attention scalars (12 of them) -------------------
__global__ void k_wec(const float* __restrict__ We,
                      const float* __restrict__ a_edge) {
    int t = threadIdx.x;
    if (t >= L_ * H_) return;
    int l = t / H_, h = t % H_;
    float s = 0.0f;
    for (int c = 0; c < C_; c++)
        s += We[l * HID_ + h * C_ + c] * a_edge[l * HID_ + h * C_ + c];
    g_wec[t] = s;
}

// ---------------- fused CSR aggregation + softmax + bias + LN-reduce ----------
// one warp per dst node; lane owns features [4*lane, 4*lane+4)
__global__ void k_agg(const float* __restrict__ bg, int l) {
    const int warp = (blockIdx.x * blockDim.x + threadIdx.x) >> 5;
    const int lane = threadIdx.x & 31;
    float s1 = 0.0f, s2 = 0.0f;

    if (warp < N_) {
        const int n  = warp;
        const int r0 = g_row[n];
        const int r1 = g_row[n + 1];
        const int h  = lane >> 3;
        const float aldh = g_ald[n * H_ + h];
        const float wech = g_wec[l * H_ + h];

        float4 acc = make_float4(0.f, 0.f, 0.f, 0.f);
        float den = 0.0f;
        for (int idx = r0; idx < r1; idx++) {
            int2 se = g_se[idx];
            int s = se.x;
            float av = __int_as_float(se.y);
            float lg = g_als[s * H_ + h] + aldh + av * wech;
            lg = fmaxf(lg, NEG_SLOPE * lg);         // leaky relu
            float ex = __expf(lg);                   // m = 0 (cancels in ratio)
            den += ex;
            float4 xv = ((const float4*)g_xh)[s * 32 + lane];
            acc.x += ex * xv.x;
            acc.y += ex * xv.y;
            acc.z += ex * xv.z;
            acc.w += ex * xv.w;
        }
        float inv = 1.0f / (den + 1e-16f);
        float4 b4 = ((const float4*)bg)[lane];
        float4 o;
        o.x = acc.x * inv + b4.x;
        o.y = acc.y * inv + b4.y;
        o.z = acc.z * inv + b4.z;
        o.w = acc.w * inv + b4.w;
        ((float4*)g_g)[n * 32 + lane] = o;
        s1 = o.x + o.y + o.z + o.w;
        s2 = o.x * o.x + o.y * o.y + o.z * o.z + o.w * o.w;
    }

    // block reduction of s1, s2
#pragma unroll
    for (int o = 16; o > 0; o >>= 1) {
        s1 += __shfl_xor_sync(0xffffffffu, s1, o);
        s2 += __shfl_xor_sync(0xffffffffu, s2, o);
    }
    __shared__ float r1[8], r2[8];
    int wl = threadIdx.x >> 5;
    if (lane == 0) { r1[wl] = s1; r2[wl] = s2; }
    __syncthreads();
    if (threadIdx.x < 8) {
        float a = r1[threadIdx.x], b = r2[threadIdx.x];
#pragma unroll
        for (int o = 4; o > 0; o >>= 1) {
            a += __shfl_xor_sync(0xffu, a, o);
            b += __shfl_xor_sync(0xffu, b, o);
        }
        if (threadIdx.x == 0) {
            atomicAdd(&g_red[0], (double)a);
            atomicAdd(&g_red[1], (double)b);
        }
    }
}

__global__ void k_stats() {
    double M = (double)N_ * (double)HID_;
    double mean = g_red[0] / M;
    double var  = g_red[1] / M - mean * mean;
    g_stats[0] = (float)mean;
    g_stats[1] = (float)(1.0 / sqrt(var + 1e-5));
}

// ---------------- apply LN + residual ReLU -----------------------------------
__global__ void k_apply(const float* __restrict__ lnw,
                        const float* __restrict__ lnb) {
    int idx = blockIdx.x * blockDim.x + threadIdx.x;
    if (idx >= N_ * 32) return;
    int q = idx & 31;
    float mean = g_stats[0], istd = g_stats[1];
    float4 g = ((float4*)g_g)[idx];
    float4 h = ((float4*)g_h)[idx];
    float4 w = ((const float4*)lnw)[q];
    float4 b = ((const float4*)lnb)[q];
    float4 o;
    o.x = fmaxf((g.x - mean) * istd * w.x + b.x + h.x, 0.0f);
    o.y = fmaxf((g.y - mean) * istd * w.y + b.y + h.y, 0.0f);
    o.z = fmaxf((g.z - mean) * istd * w.z + b.z + h.z, 0.0f);
    o.w = fmaxf((g.w - mean) * istd * w.w + b.w + h.w, 0.0f);
    ((float4*)g_h)[idx] = o;
}

// ---------------- output projection ------------------------------------------
__global__ void k_out(const float* __restrict__ Wout,
                      const float* __restrict__ bout,
                      float* __restrict__ out) {
    __shared__ float ws[HID_ * OUT_];
    __shared__ float bs[OUT_];
    for (int i = threadIdx.x; i < HID_ * OUT_; i += blockDim.x) ws[i] = Wout[i];
    if (threadIdx.x < OUT_) bs[threadIdx.x] = bout[threadIdx.x];
    __syncthreads();
    int n = blockIdx.x * blockDim.x + threadIdx.x;
    if (n >= N_) return;
    float acc[OUT_];
#pragma unroll
    for (int j = 0; j < OUT_; j++) acc[j] = bs[j];
    const float4* hr = (const float4*)(g_h + n * HID_);
#pragma unroll 8
    for (int k4 = 0; k4 < 32; k4++) {
        float4 hv = hr[k4];
        float hvv[4] = {hv.x, hv.y, hv.z, hv.w};
#pragma unroll
        for (int t = 0; t < 4; t++) {
            int k = k4 * 4 + t;
#pragma unroll
            for (int j = 0; j < OUT_; j++) acc[j] += hvv[t] * ws[k * OUT_ + j];
        }
    }
#pragma unroll
    for (int j = 0; j < OUT_; j++) out[n * OUT_ + j] = acc[j];
}

// ---------------- launch ------------------------------------------------------
extern "C" void kernel_launch(void* const* d_in, const int* in_sizes, int n_in,
                              void* d_out, int out_size) {
    const float* x      = (const float*)d_in[0];
    const int*   ei     = (const int*)d_in[1];   // int32 (JAX x64 disabled)
    const float* ea     = (const float*)d_in[2];
    const float* Win    = (const float*)d_in[3];
    const float* b_in   = (const float*)d_in[4];
    const float* Wg     = (const float*)d_in[5];
    const float* bg     = (const float*)d_in[6];
    const float* a_src  = (const float*)d_in[7];
    const float* a_dst  = (const float*)d_in[8];
    const float* We     = (const float*)d_in[9];
    const float* a_edge = (const float*)d_in[10];
    const float* ln_w   = (const float*)d_in[11];
    const float* ln_b   = (const float*)d_in[12];
    const float* Wout   = (const float*)d_in[13];
    const float* bout   = (const float*)d_in[14];
    float*       out    = (float*)d_out;

    // CSR build (dst-sorted, self loops first per node)
    k_cnt_init     <<<(N_ + 255) / 256, 256>>>();
    k_hist         <<<(E_ + 255) / 256, 256>>>(ei, ea);
    k_scan1        <<<NBSCAN, 1024>>>();
    k_scan2        <<<1, 128>>>();
    k_scan3        <<<(N_ + 255) / 256, 256>>>();
    k_selfloop_fin <<<(N_ + 255) / 256, 256>>>();
    k_scatter_self <<<(N_ + 255) / 256, 256>>>();
    k_scatter_edges<<<(E_ + 255) / 256, 256>>>(ei, ea);

    k_ingemm<<<(N_ + 63) / 64, 256>>>(x, Win, b_in);
    k_wec   <<<1, 32>>>(We, a_edge);

    for (int l = 0; l < L_; l++) {
        k_gemm <<<(N_ + 63) / 64, 256>>>(Wg + l * HID_ * HID_);
        k_attn <<<(N_ * H_ + 255) / 256, 256>>>(a_src + l * H_ * C_,
                                                a_dst + l * H_ * C_);
        k_agg  <<<(N_ + 7) / 8, 256>>>(bg + l * HID_, l);
        k_stats<<<1, 1>>>();
        k_apply<<<(N_ * 32 + 255) / 256, 256>>>(ln_w + l * HID_,
                                                ln_b + l * HID_);
    }
    k_out<<<(N_ + 255) / 256, 256>>>(Wout, bout, out);
}

// round 4
// speedup vs baseline: 2.6464x; 1.3387x over previous
#include <cuda_runtime.h>
#include <math.h>
#include <stdint.h>

// Problem constants (shapes fixed by the dataset)
#define N_   100000
#define E_   800000
#define ET_  900000      // E + N self loops
#define HID_ 128
#define H_   4
#define C_   32
#define L_   3
#define OUT_ 5
#define NEG_SLOPE 0.2f
#define NBSCAN 98        // ceil(N_/1024)
#define GBLK  ((N_ + 127) / 128)

// ---------------- scratch (static device globals; no allocation) -------------
__device__ __align__(16) float  g_h   [N_ * HID_];   // current node features
__device__ __align__(16) float  g_xh  [N_ * HID_];   // xh = h @ Wg[l]
__device__ __align__(16) float  g_g   [N_ * HID_];   // post-aggregation g
__device__ __align__(16) float  g_als [N_ * H_];
__device__ __align__(16) float  g_ald [N_ * H_];
__device__ __align__(16) float  g_loop[N_];          // self-loop attr
__device__ __align__(16) float  g_wec [L_ * H_];     // a_edge . We per (l,h)
__device__ __align__(16) double g_red [2];           // sum, sumsq for layernorm
__device__ __align__(16) float  g_stats[2];          // mean, inv_std
// CSR
__device__ __align__(16) int    g_cnt [N_];
__device__ __align__(16) int    g_row [N_ + 1];
__device__ __align__(16) int    g_fill[N_];
__device__ __align__(16) int    g_bsum[NBSCAN];
__device__ __align__(16) int    g_bsumx[128];
__device__ __align__(16) int2   g_se  [ET_];         // (src, edge_attr bits) dst-sorted

// ---------------- helpers -----------------------------------------------------
__device__ __forceinline__ float totf32(float x) {
    uint32_t u;
    asm("cvt.rna.tf32.f32 %0, %1;" : "=r"(u) : "f"(x));
    return __uint_as_float(u);
}

// ---------------- CSR build ---------------------------------------------------
__global__ void k_cnt_init() {
    int i = blockIdx.x * blockDim.x + threadIdx.x;
    if (i < N_) { g_cnt[i] = 1; g_loop[i] = 0.0f; }   // 1 = self loop
}

__global__ void k_hist(const int* __restrict__ ei, const float* __restrict__ ea) {
    int e = blockIdx.x * blockDim.x + threadIdx.x;
    if (e < E_) {
        int d = ei[E_ + e];
        atomicAdd(&g_cnt[d], 1);
        atomicAdd(&g_loop[d], ea[e]);
    }
}

__global__ void k_scan1() {
    __shared__ int wtot[32];
    int i = blockIdx.x * 1024 + threadIdx.x;
    int lane = threadIdx.x & 31, wid = threadIdx.x >> 5;
    int v = (i < N_) ? g_cnt[i] : 0;
    int inc = v;
#pragma unroll
    for (int o = 1; o < 32; o <<= 1) {
        int t = __shfl_up_sync(0xffffffffu, inc, o);
        if (lane >= o) inc += t;
    }
    if (lane == 31) wtot[wid] = inc;
    __syncthreads();
    if (wid == 0) {
        int w = wtot[lane];
        int winc = w;
#pragma unroll
        for (int o = 1; o < 32; o <<= 1) {
            int t = __shfl_up_sync(0xffffffffu, winc, o);
            if (lane >= o) winc += t;
        }
        wtot[lane] = winc - w;          // exclusive warp offsets
    }
    __syncthreads();
    int excl = inc - v + wtot[wid];
    if (i < N_) g_row[i] = excl;        // block-local exclusive
    if (threadIdx.x == 1023) g_bsum[blockIdx.x] = excl + v;
}

__global__ void k_scan2() {
    __shared__ int sh[128];
    int t = threadIdx.x;
    int v = (t < NBSCAN) ? g_bsum[t] : 0;
    sh[t] = v;
    __syncthreads();
    for (int o = 1; o < 128; o <<= 1) {
        int x = (t >= o) ? sh[t - o] : 0;
        __syncthreads();
        sh[t] += x;
        __syncthreads();
    }
    g_bsumx[t] = sh[t] - v;             // exclusive
}

__global__ void k_scan3() {
    int i = blockIdx.x * blockDim.x + threadIdx.x;
    if (i < N_) g_row[i] += g_bsumx[i >> 10];
    if (i == 0) g_row[N_] = ET_;
}

__global__ void k_selfloop_fin() {      // loop attr = mean of incoming
    int i = blockIdx.x * blockDim.x + threadIdx.x;
    if (i < N_) g_loop[i] = g_loop[i] / fmaxf((float)(g_cnt[i] - 1), 1.0f);
}

__global__ void k_scatter_self() {
    int i = blockIdx.x * blockDim.x + threadIdx.x;
    if (i < N_) {
        g_fill[i] = 1;
        int2 se; se.x = i; se.y = __float_as_int(g_loop[i]);
        g_se[g_row[i]] = se;
    }
}

__global__ void k_scatter_edges(const int* __restrict__ ei,
                                const float* __restrict__ ea) {
    int e = blockIdx.x * blockDim.x + threadIdx.x;
    if (e < E_) {
        int d = ei[E_ + e];
        int pos = g_row[d] + atomicAdd(&g_fill[d], 1);
        int2 se; se.x = ei[e]; se.y = __float_as_int(ea[e]);
        g_se[pos] = se;
    }
}

// ---------------- input projection: h = x @ Win + b_in (tiled FFMA) -----------
__global__ void k_ingemm(const float* __restrict__ x,
                         const float* __restrict__ Win,
                         const float* __restrict__ bin) {
    __shared__ float As[64][33];
    __shared__ float Bs[32][128];
    const int tx = threadIdx.x & 15;
    const int ty = threadIdx.x >> 4;
    const int row0 = blockIdx.x * 64;

    {
        int kk = threadIdx.x & 31;
        int rb = threadIdx.x >> 5;
#pragma unroll
        for (int i = 0; i < 8; i++) {
            int r = rb + i * 8;
            int gr = row0 + r;
            As[r][kk] = (gr < N_) ? x[gr * 32 + kk] : 0.0f;
        }
    }
    {
        int col = threadIdx.x & 127;
        int kb  = threadIdx.x >> 7;
#pragma unroll
        for (int i = 0; i < 16; i++) {
            int kk = kb + i * 2;
            Bs[kk][col] = Win[kk * HID_ + col];
        }
    }
    __syncthreads();

    float acc[4][8];
#pragma unroll
    for (int i = 0; i < 4; i++)
#pragma unroll
        for (int j = 0; j < 8; j++) acc[i][j] = 0.0f;
#pragma unroll
    for (int k = 0; k < 32; k++) {
        float a[4], b[8];
#pragma unroll
        for (int i = 0; i < 4; i++) a[i] = As[ty + i * 16][k];
#pragma unroll
        for (int j = 0; j < 8; j++) b[j] = Bs[k][tx + j * 16];
#pragma unroll
        for (int i = 0; i < 4; i++)
#pragma unroll
            for (int j = 0; j < 8; j++) acc[i][j] += a[i] * b[j];
    }
#pragma unroll
    for (int i = 0; i < 4; i++) {
        int gr = row0 + ty + i * 16;
        if (gr < N_) {
#pragma unroll
            for (int j = 0; j < 8; j++)
                g_h[gr * HID_ + tx + j * 16] = acc[i][j] + bin[tx + j * 16];
        }
    }
}

// ---------------- TF32 tensor-core GEMM: g_xh = g_h @ B (N_ x 128 x 128) ------
// block: 256 thr (8 warps), tile 128x128, K chunks of 32, mma.m16n8k8.tf32
__global__ void __launch_bounds__(256) k_gemm_tc(const float* __restrict__ Bw) {
    __shared__ float As[128][36];    // [row][k], pad 36 -> fragment loads conflict-free
    __shared__ float Bs[32][136];    // [k][col], pad 136 -> conflict-free

    const int t    = threadIdx.x;
    const int lane = t & 31;
    const int wid  = t >> 5;
    const int g    = lane >> 2;      // 0..7
    const int tg   = lane & 3;       // 0..3
    const int wm   = wid & 1;        // warp row (2 x 64 rows)
    const int wn   = wid >> 1;       // warp col (4 x 32 cols)
    const int row0 = blockIdx.x * 128;

    float c[4][4][4];
#pragma unroll
    for (int i = 0; i < 4; i++)
#pragma unroll
        for (int j = 0; j < 4; j++)
#pragma unroll
            for (int r = 0; r < 4; r++) c[i][j][r] = 0.0f;

    float4 stA[4], stB[4];

    // prefetch chunk 0
    {
        const int k0 = 0;
#pragma unroll
        for (int it = 0; it < 4; it++) {
            int f = t + it * 256;
            int row = f >> 3, q = f & 7;
            int gr = row0 + row;
            stA[it] = (gr < N_) ? *(const float4*)(g_h + gr * HID_ + k0 + q * 4)
                                : make_float4(0.f, 0.f, 0.f, 0.f);
        }
#pragma unroll
        for (int it = 0; it < 4; it++) {
            int f = t + it * 256;
            int k = f >> 5, cq = f & 31;
            stB[it] = *(const float4*)(Bw + (k0 + k) * HID_ + cq * 4);
        }
    }

    for (int kc = 0; kc < 4; kc++) {
        __syncthreads();
        // store staged chunk (with tf32 rounding)
#pragma unroll
        for (int it = 0; it < 4; it++) {
            int f = t + it * 256;
            int row = f >> 3, q = f & 7;
            float4 v = stA[it];
            v.x = totf32(v.x); v.y = totf32(v.y);
            v.z = totf32(v.z); v.w = totf32(v.w);
            *(float4*)&As[row][q * 4] = v;
        }
#pragma unroll
        for (int it = 0; it < 4; it++) {
            int f = t + it * 256;
            int k = f >> 5, cq = f & 31;
            float4 v = stB[it];
            v.x = totf32(v.x); v.y = totf32(v.y);
            v.z = totf32(v.z); v.w = totf32(v.w);
            *(float4*)&Bs[k][cq * 4] = v;
        }
        __syncthreads();

        // prefetch next chunk while computing
        if (kc < 3) {
            const int k0 = (kc + 1) * 32;
#pragma unroll
            for (int it = 0; it < 4; it++) {
                int f = t + it * 256;
                int row = f >> 3, q = f & 7;
                int gr = row0 + row;
                stA[it] = (gr < N_) ? *(const float4*)(g_h + gr * HID_ + k0 + q * 4)
                                    : make_float4(0.f, 0.f, 0.f, 0.f);
            }
#pragma unroll
            for (int it = 0; it < 4; it++) {
                int f = t + it * 256;
                int k = f >> 5, cq = f & 31;
                stB[it] = *(const float4*)(Bw + (k0 + k) * HID_ + cq * 4);
            }
        }

        // compute: 4 mma k-steps of 8
#pragma unroll
        for (int k8 = 0; k8 < 4; k8++) {
            const int kk = k8 * 8;
            uint32_t a[4][4], b[4][2];
#pragma unroll
            for (int mi = 0; mi < 4; mi++) {
                int r = wm * 64 + mi * 16 + g;
                a[mi][0] = __float_as_uint(As[r    ][kk + tg    ]);
                a[mi][1] = __float_as_uint(As[r + 8][kk + tg    ]);
                a[mi][2] = __float_as_uint(As[r    ][kk + tg + 4]);
                a[mi][3] = __float_as_uint(As[r + 8][kk + tg + 4]);
            }
#pragma unroll
            for (int ni = 0; ni < 4; ni++) {
                int cc = wn * 32 + ni * 8 + g;
                b[ni][0] = __float_as_uint(Bs[kk + tg    ][cc]);
                b[ni][1] = __float_as_uint(Bs[kk + tg + 4][cc]);
            }
#pragma unroll
            for (int mi = 0; mi < 4; mi++)
#pragma unroll
                for (int ni = 0; ni < 4; ni++)
                    asm volatile(
                        "mma.sync.aligned.m16n8k8.row.col.f32.tf32.tf32.f32 "
                        "{%0,%1,%2,%3}, {%4,%5,%6,%7}, {%8,%9}, {%0,%1,%2,%3};"
                        : "+f"(c[mi][ni][0]), "+f"(c[mi][ni][1]),
                          "+f"(c[mi][ni][2]), "+f"(c[mi][ni][3])
                        : "r"(a[mi][0]), "r"(a[mi][1]), "r"(a[mi][2]), "r"(a[mi][3]),
                          "r"(b[ni][0]), "r"(b[ni][1]));
        }
    }

    // epilogue
#pragma unroll
    for (int mi = 0; mi < 4; mi++) {
        int r = row0 + wm * 64 + mi * 16 + g;
#pragma unroll
        for (int ni = 0; ni < 4; ni++) {
            int cc = wn * 32 + ni * 8 + tg * 2;
            if (r < N_)
                *(float2*)(g_xh + r * HID_ + cc) =
                    make_float2(c[mi][ni][0], c[mi][ni][1]);
            if (r + 8 < N_)
                *(float2*)(g_xh + (r + 8) * HID_ + cc) =
                    make_float2(c[mi][ni][2], c[mi][ni][3]);
        }
    }
}

// ---------------- per-node attention coefficients (+ g_red reset) -------------
__global__ void k_attn(const float* __restrict__ a_src,
                       const float* __restrict__ a_dst) {
    int t = blockIdx.x * blockDim.x + threadIdx.x;
    if (t == 0) { g_red[0] = 0.0; g_red[1] = 0.0; }
    if (t >= N_ * H_) return;
    int n = t >> 2, h = t & 3;
    const float4* xr  = (const float4*)(g_xh + n * HID_ + h * C_);
    const float4* as4 = (const float4*)(a_src + h * C_);
    const float4* ad4 = (const float4*)(a_dst + h * C_);
    float s = 0.0f, d = 0.0f;
#pragma unroll
    for (int i = 0; i < 8; i++) {
        float4 xv = xr[i], av = as4[i], dv = ad4[i];
        s += xv.x * av.x + xv.y * av.y + xv.z * av.z + xv.w * av.w;
        d += xv.x * dv.x + xv.y * dv.y + xv.z * dv.z + xv.w * dv.w;
    }
    g_als[t] = s;
    g_ald[t] = d;
}

// ---------------- edge-attr attention scalars (12 of them) -------------------
__global__ void k_wec(const float* __restrict__ We,
                      const float* __restrict__ a_edge) {
    int t = threadIdx.x;
    if (t >= L_ * H_) return;
    int l = t / H_, h = t % H_;
    float s = 0.0f;
    for (int c = 0; c < C_; c++)
        s += We[l * HID_ + h * C_ + c] * a_edge[l * HID_ + h * C_ + c];
    g_wec[t] = s;
}

// ---------------- fused CSR aggregation + softmax + bias + LN-reduce ----------
// one warp per dst node; lane owns features [4*lane, 4*lane+4)
__global__ void k_agg(const float* __restrict__ bg, int l) {
    const int warp = (blockIdx.x * blockDim.x + threadIdx.x) >> 5;
    const int lane = threadIdx.x & 31;
    float s1 = 0.0f, s2 = 0.0f;

    if (warp < N_) {
        const int n  = warp;
        const int r0 = g_row[n];
        const int r1 = g_row[n + 1];
        const int h  = lane >> 3;
        const float aldh = g_ald[n * H_ + h];
        const float wech = g_wec[l * H_ + h];

        float4 acc = make_float4(0.f, 0.f, 0.f, 0.f);
        float den = 0.0f;
        for (int idx = r0; idx < r1; idx++) {
            int2 se = g_se[idx];
            int s = se.x;
            float av = __int_as_float(se.y);
            float lg = g_als[s * H_ + h] + aldh + av * wech;
            lg = fmaxf(lg, NEG_SLOPE * lg);          // leaky relu
            float ex = __expf(lg);                    // m = 0 (cancels in ratio)
            den += ex;
            float4 xv = ((const float4*)g_xh)[s * 32 + lane];
            acc.x += ex * xv.x;
            acc.y += ex * xv.y;
            acc.z += ex * xv.z;
            acc.w += ex * xv.w;
        }
        float inv = 1.0f / (den + 1e-16f);
        float4 b4 = ((const float4*)bg)[lane];
        float4 o;
        o.x = acc.x * inv + b4.x;
        o.y = acc.y * inv + b4.y;
        o.z = acc.z * inv + b4.z;
        o.w = acc.w * inv + b4.w;
        ((float4*)g_g)[n * 32 + lane] = o;
        s1 = o.x + o.y + o.z + o.w;
        s2 = o.x * o.x + o.y * o.y + o.z * o.z + o.w * o.w;
    }

#pragma unroll
    for (int o = 16; o > 0; o >>= 1) {
        s1 += __shfl_xor_sync(0xffffffffu, s1, o);
        s2 += __shfl_xor_sync(0xffffffffu, s2, o);
    }
    __shared__ float r1[8], r2[8];
    int wl = threadIdx.x >> 5;
    if (lane == 0) { r1[wl] = s1; r2[wl] = s2; }
    __syncthreads();
    if (threadIdx.x < 8) {
        float a = r1[threadIdx.x], b = r2[threadIdx.x];
#pragma unroll
        for (int o = 4; o > 0; o >>= 1) {
            a += __shfl_xor_sync(0xffu, a, o);
            b += __shfl_xor_sync(0xffu, b, o);
        }
        if (threadIdx.x == 0) {
            atomicAdd(&g_red[0], (double)a);
            atomicAdd(&g_red[1], (double)b);
        }
    }
}

__global__ void k_stats() {
    double M = (double)N_ * (double)HID_;
    double mean = g_red[0] / M;
    double var  = g_red[1] / M - mean * mean;
    g_stats[0] = (float)mean;
    g_stats[1] = (float)(1.0 / sqrt(var + 1e-5));
}

// ---------------- apply LN + residual ReLU -----------------------------------
__global__ void k_apply(const float* __restrict__ lnw,
                        const float* __restrict__ lnb) {
    int idx = blockIdx.x * blockDim.x + threadIdx.x;
    if (idx >= N_ * 32) return;
    int q = idx & 31;
    float mean = g_stats[0], istd = g_stats[1];
    float4 g = ((float4*)g_g)[idx];
    float4 h = ((float4*)g_h)[idx];
    float4 w = ((const float4*)lnw)[q];
    float4 b = ((const float4*)lnb)[q];
    float4 o;
    o.x = fmaxf((g.x - mean) * istd * w.x + b.x + h.x, 0.0f);
    o.y = fmaxf((g.y - mean) * istd * w.y + b.y + h.y, 0.0f);
    o.z = fmaxf((g.z - mean) * istd * w.z + b.z + h.z, 0.0f);
    o.w = fmaxf((g.w - mean) * istd * w.w + b.w + h.w, 0.0f);
    ((float4*)g_h)[idx] = o;
}

// ---------------- output projection ------------------------------------------
__global__ void k_out(const float* __restrict__ Wout,
                      const float* __restrict__ bout,
                      float* __restrict__ out) {
    __shared__ float ws[HID_ * OUT_];
    __shared__ float bs[OUT_];
    for (int i = threadIdx.x; i < HID_ * OUT_; i += blockDim.x) ws[i] = Wout[i];
    if (threadIdx.x < OUT_) bs[threadIdx.x] = bout[threadIdx.x];
    __syncthreads();
    int n = blockIdx.x * blockDim.x + threadIdx.x;
    if (n >= N_) return;
    float acc[OUT_];
#pragma unroll
    for (int j = 0; j < OUT_; j++) acc[j] = bs[j];
    const float4* hr = (const float4*)(g_h + n * HID_);
#pragma unroll 8
    for (int k4 = 0; k4 < 32; k4++) {
        float4 hv = hr[k4];
        float hvv[4] = {hv.x, hv.y, hv.z, hv.w};
#pragma unroll
        for (int t = 0; t < 4; t++) {
            int k = k4 * 4 + t;
#pragma unroll
            for (int j = 0; j < OUT_; j++) acc[j] += hvv[t] * ws[k * OUT_ + j];
        }
    }
#pragma unroll
    for (int j = 0; j < OUT_; j++) out[n * OUT_ + j] = acc[j];
}

// ---------------- launch ------------------------------------------------------
extern "C" void kernel_launch(void* const* d_in, const int* in_sizes, int n_in,
                              void* d_out, int out_size) {
    const float* x      = (const float*)d_in[0];
    const int*   ei     = (const int*)d_in[1];   // int32 (JAX x64 disabled)
    const float* ea     = (const float*)d_in[2];
    const float* Win    = (const float*)d_in[3];
    const float* b_in   = (const float*)d_in[4];
    const float* Wg     = (const float*)d_in[5];
    const float* bg     = (const float*)d_in[6];
    const float* a_src  = (const float*)d_in[7];
    const float* a_dst  = (const float*)d_in[8];
    const float* We     = (const float*)d_in[9];
    const float* a_edge = (const float*)d_in[10];
    const float* ln_w   = (const float*)d_in[11];
    const float* ln_b   = (const float*)d_in[12];
    const float* Wout   = (const float*)d_in[13];
    const float* bout   = (const float*)d_in[14];
    float*       out    = (float*)d_out;

    // CSR build (dst-sorted, self loops first per node)
    k_cnt_init     <<<(N_ + 255) / 256, 256>>>();
    k_hist         <<<(E_ + 255) / 256, 256>>>(ei, ea);
    k_scan1        <<<NBSCAN, 1024>>>();
    k_scan2        <<<1, 128>>>();
    k_scan3        <<<(N_ + 255) / 256, 256>>>();
    k_selfloop_fin <<<(N_ + 255) / 256, 256>>>();
    k_scatter_self <<<(N_ + 255) / 256, 256>>>();
    k_scatter_edges<<<(E_ + 255) / 256, 256>>>(ei, ea);

    k_ingemm<<<(N_ + 63) / 64, 256>>>(x, Win, b_in);
    k_wec   <<<1, 32>>>(We, a_edge);

    for (int l = 0; l < L_; l++) {
        k_gemm_tc<<<GBLK, 256>>>(Wg + l * HID_ * HID_);
        k_attn <<<(N_ * H_ + 255) / 256, 256>>>(a_src + l * H_ * C_,
                                                a_dst + l * H_ * C_);
        k_agg  <<<(N_ + 7) / 8, 256>>>(bg + l * HID_, l);
        k_stats<<<1, 1>>>();
        k_apply<<<(N_ * 32 + 255) / 256, 256>>>(ln_w + l * HID_,
                                                ln_b + l * HID_);
    }
    k_out<<<(N_ + 255) / 256, 256>>>(Wout, bout, out);
}

// round 5
// speedup vs baseline: 2.7373x; 1.0343x over previous
#include <cuda_runtime.h>
#include <math.h>
#include <stdint.h>

// Problem constants (shapes fixed by the dataset)
#define N_   100000
#define E_   800000
#define ET_  900000      // E + N self loops
#define HID_ 128
#define H_   4
#define C_   32
#define L_   3
#define OUT_ 5
#define NEG_SLOPE 0.2f
#define NBSCAN 98        // ceil(N_/1024)
#define GBLK  ((N_ + 127) / 128)

// ---------------- scratch (static device globals; no allocation) -------------
__device__ __align__(16) float  g_h   [N_ * HID_];   // current node features
__device__ __align__(16) float  g_xh  [N_ * HID_];   // xh = h @ Wg[l]
__device__ __align__(16) float  g_g   [N_ * HID_];   // post-aggregation g
__device__ __align__(16) float  g_als [N_ * H_];
__device__ __align__(16) float  g_ald [N_ * H_];
__device__ __align__(16) float  g_loop[N_];          // self-loop attr accumulator
__device__ __align__(16) float  g_wec [L_ * H_];     // a_edge . We per (l,h)
__device__ __align__(16) double g_red [2];           // sum, sumsq for layernorm
__device__ __align__(16) float  g_stats[2];          // mean, inv_std
// CSR
__device__ __align__(16) int    g_cnt [N_];
__device__ __align__(16) int    g_row [N_ + 1];
__device__ __align__(16) int    g_fill[N_];
__device__ __align__(16) int    g_bsum[NBSCAN];
__device__ __align__(16) int    g_bsumx[128];
__device__ __align__(16) int2   g_se  [ET_];         // (src, edge_attr bits) dst-sorted

// ---------------- helpers -----------------------------------------------------
__device__ __forceinline__ float totf32(float x) {
    uint32_t u;
    asm("cvt.rna.tf32.f32 %0, %1;" : "=r"(u) : "f"(x));
    return __uint_as_float(u);
}

// ---------------- CSR build ---------------------------------------------------
__global__ void k_cnt_init() {
    int i = blockIdx.x * blockDim.x + threadIdx.x;
    if (i < N_) { g_cnt[i] = 1; g_loop[i] = 0.0f; }   // 1 = self loop
}

__global__ void k_hist(const int* __restrict__ ei, const float* __restrict__ ea) {
    int e = blockIdx.x * blockDim.x + threadIdx.x;
    if (e < E_) {
        int d = ei[E_ + e];
        atomicAdd(&g_cnt[d], 1);
        atomicAdd(&g_loop[d], ea[e]);
    }
}

__global__ void k_scan1() {
    __shared__ int wtot[32];
    int i = blockIdx.x * 1024 + threadIdx.x;
    int lane = threadIdx.x & 31, wid = threadIdx.x >> 5;
    int v = (i < N_) ? g_cnt[i] : 0;
    int inc = v;
#pragma unroll
    for (int o = 1; o < 32; o <<= 1) {
        int t = __shfl_up_sync(0xffffffffu, inc, o);
        if (lane >= o) inc += t;
    }
    if (lane == 31) wtot[wid] = inc;
    __syncthreads();
    if (wid == 0) {
        int w = wtot[lane];
        int winc = w;
#pragma unroll
        for (int o = 1; o < 32; o <<= 1) {
            int t = __shfl_up_sync(0xffffffffu, winc, o);
            if (lane >= o) winc += t;
        }
        wtot[lane] = winc - w;          // exclusive warp offsets
    }
    __syncthreads();
    int excl = inc - v + wtot[wid];
    if (i < N_) g_row[i] = excl;        // block-local exclusive
    if (threadIdx.x == 1023) g_bsum[blockIdx.x] = excl + v;
}

__global__ void k_scan2() {
    __shared__ int sh[128];
    int t = threadIdx.x;
    int v = (t < NBSCAN) ? g_bsum[t] : 0;
    sh[t] = v;
    __syncthreads();
    for (int o = 1; o < 128; o <<= 1) {
        int x = (t >= o) ? sh[t - o] : 0;
        __syncthreads();
        sh[t] += x;
        __syncthreads();
    }
    g_bsumx[t] = sh[t] - v;             // exclusive
}

// scan finalize + self-loop attr + self-loop scatter (fused per-node)
__global__ void k_node_fin() {
    int i = blockIdx.x * blockDim.x + threadIdx.x;
    if (i < N_) {
        int row = g_row[i] + g_bsumx[i >> 10];
        g_row[i] = row;
        float lp = g_loop[i] / fmaxf((float)(g_cnt[i] - 1), 1.0f);
        g_fill[i] = 1;
        int2 se; se.x = i; se.y = __float_as_int(lp);
        g_se[row] = se;
    }
    if (i == 0) g_row[N_] = ET_;
}

__global__ void k_scatter_edges(const int* __restrict__ ei,
                                const float* __restrict__ ea) {
    int e = blockIdx.x * blockDim.x + threadIdx.x;
    if (e < E_) {
        int d = ei[E_ + e];
        int pos = g_row[d] + atomicAdd(&g_fill[d], 1);
        int2 se; se.x = ei[e]; se.y = __float_as_int(ea[e]);
        g_se[pos] = se;
    }
}

// ---------------- input projection: h = x @ Win + b_in (tiled FFMA) -----------
__global__ void k_ingemm(const float* __restrict__ x,
                         const float* __restrict__ Win,
                         const float* __restrict__ bin) {
    __shared__ float As[64][33];
    __shared__ float Bs[32][128];
    const int tx = threadIdx.x & 15;
    const int ty = threadIdx.x >> 4;
    const int row0 = blockIdx.x * 64;

    {
        int kk = threadIdx.x & 31;
        int rb = threadIdx.x >> 5;
#pragma unroll
        for (int i = 0; i < 8; i++) {
            int r = rb + i * 8;
            int gr = row0 + r;
            As[r][kk] = (gr < N_) ? x[gr * 32 + kk] : 0.0f;
        }
    }
    {
        int col = threadIdx.x & 127;
        int kb  = threadIdx.x >> 7;
#pragma unroll
        for (int i = 0; i < 16; i++) {
            int kk = kb + i * 2;
            Bs[kk][col] = Win[kk * HID_ + col];
        }
    }
    __syncthreads();

    float acc[4][8];
#pragma unroll
    for (int i = 0; i < 4; i++)
#pragma unroll
        for (int j = 0; j < 8; j++) acc[i][j] = 0.0f;
#pragma unroll
    for (int k = 0; k < 32; k++) {
        float a[4], b[8];
#pragma unroll
        for (int i = 0; i < 4; i++) a[i] = As[ty + i * 16][k];
#pragma unroll
        for (int j = 0; j < 8; j++) b[j] = Bs[k][tx + j * 16];
#pragma unroll
        for (int i = 0; i < 4; i++)
#pragma unroll
            for (int j = 0; j < 8; j++) acc[i][j] += a[i] * b[j];
    }
#pragma unroll
    for (int i = 0; i < 4; i++) {
        int gr = row0 + ty + i * 16;
        if (gr < N_) {
#pragma unroll
            for (int j = 0; j < 8; j++)
                g_h[gr * HID_ + tx + j * 16] = acc[i][j] + bin[tx + j * 16];
        }
    }
}

// ---------------- TF32 TC GEMM + fused apply (prologue) + fused attn (epi) ----
// block: 256 thr (8 warps), tile 128x128, K chunks of 32, mma.m16n8k8.tf32
// fuse_apply=1: A rows are h' = relu(LN(g_g)+g_h); h' also written back to g_h.
// epilogue: warp (wm,wn) owns cols of head wn -> computes g_als/g_ald rows.
__global__ void __launch_bounds__(256) k_gemm_tc(
    const float* __restrict__ Bw,
    const float* __restrict__ asrc, const float* __restrict__ adst,
    const float* __restrict__ lnw,  const float* __restrict__ lnb,
    int fuse_apply)
{
    __shared__ float As[128][36];
    __shared__ float Bs[32][136];

    const int t    = threadIdx.x;
    const int lane = t & 31;
    const int wid  = t >> 5;
    const int g    = lane >> 2;      // 0..7
    const int tg   = lane & 3;       // 0..3
    const int wm   = wid & 1;        // warp row (2 x 64 rows)
    const int wn   = wid >> 1;       // warp col (4 x 32 cols) == head id
    const int row0 = blockIdx.x * 128;

    const float mean = g_stats[0], istd = g_stats[1];

    float c[4][4][4];
#pragma unroll
    for (int i = 0; i < 4; i++)
#pragma unroll
        for (int j = 0; j < 4; j++)
#pragma unroll
            for (int r = 0; r < 4; r++) c[i][j][r] = 0.0f;

    float4 stA[4], stB[4];

    // ---- loader lambda-ish (manually inlined twice) ----
#define LOAD_CHUNK(K0)                                                         \
    {                                                                          \
        const int k0 = (K0);                                                   \
        _Pragma("unroll")                                                      \
        for (int it = 0; it < 4; it++) {                                       \
            int f = t + it * 256;                                              \
            int row = f >> 3, q = f & 7;                                       \
            int gr = row0 + row;                                               \
            float4 v = make_float4(0.f, 0.f, 0.f, 0.f);                        \
            if (gr < N_) {                                                     \
                if (fuse_apply) {                                              \
                    float4 gv = *(const float4*)(g_g + gr * HID_ + k0 + q * 4);\
                    float4 hv = *(const float4*)(g_h + gr * HID_ + k0 + q * 4);\
                    float4 wv = *(const float4*)(lnw + k0 + q * 4);            \
                    float4 bv = *(const float4*)(lnb + k0 + q * 4);            \
                    v.x = fmaxf((gv.x - mean) * istd * wv.x + bv.x + hv.x, 0.f);\
                    v.y = fmaxf((gv.y - mean) * istd * wv.y + bv.y + hv.y, 0.f);\
                    v.z = fmaxf((gv.z - mean) * istd * wv.z + bv.z + hv.z, 0.f);\
                    v.w = fmaxf((gv.w - mean) * istd * wv.w + bv.w + hv.w, 0.f);\
                    *(float4*)(g_h + gr * HID_ + k0 + q * 4) = v;              \
                } else {                                                       \
                    v = *(const float4*)(g_h + gr * HID_ + k0 + q * 4);        \
                }                                                              \
            }                                                                  \
            stA[it] = v;                                                       \
        }                                                                      \
        _Pragma("unroll")                                                      \
        for (int it = 0; it < 4; it++) {                                       \
            int f = t + it * 256;                                              \
            int k = f >> 5, cq = f & 31;                                       \
            stB[it] = *(const float4*)(Bw + (k0 + k) * HID_ + cq * 4);         \
        }                                                                      \
    }

    LOAD_CHUNK(0)

    for (int kc = 0; kc < 4; kc++) {
        __syncthreads();
#pragma unroll
        for (int it = 0; it < 4; it++) {
            int f = t + it * 256;
            int row = f >> 3, q = f & 7;
            float4 v = stA[it];
            v.x = totf32(v.x); v.y = totf32(v.y);
            v.z = totf32(v.z); v.w = totf32(v.w);
            *(float4*)&As[row][q * 4] = v;
        }
#pragma unroll
        for (int it = 0; it < 4; it++) {
            int f = t + it * 256;
            int k = f >> 5, cq = f & 31;
            float4 v = stB[it];
            v.x = totf32(v.x); v.y = totf32(v.y);
            v.z = totf32(v.z); v.w = totf32(v.w);
            *(float4*)&Bs[k][cq * 4] = v;
        }
        __syncthreads();

        if (kc < 3) LOAD_CHUNK((kc + 1) * 32)

#pragma unroll
        for (int k8 = 0; k8 < 4; k8++) {
            const int kk = k8 * 8;
            uint32_t a[4][4], b[4][2];
#pragma unroll
            for (int mi = 0; mi < 4; mi++) {
                int r = wm * 64 + mi * 16 + g;
                a[mi][0] = __float_as_uint(As[r    ][kk + tg    ]);
                a[mi][1] = __float_as_uint(As[r + 8][kk + tg    ]);
                a[mi][2] = __float_as_uint(As[r    ][kk + tg + 4]);
                a[mi][3] = __float_as_uint(As[r + 8][kk + tg + 4]);
            }
#pragma unroll
            for (int ni = 0; ni < 4; ni++) {
                int cc = wn * 32 + ni * 8 + g;
                b[ni][0] = __float_as_uint(Bs[kk + tg    ][cc]);
                b[ni][1] = __float_as_uint(Bs[kk + tg + 4][cc]);
            }
#pragma unroll
            for (int mi = 0; mi < 4; mi++)
#pragma unroll
                for (int ni = 0; ni < 4; ni++)
                    asm volatile(
                        "mma.sync.aligned.m16n8k8.row.col.f32.tf32.tf32.f32 "
                        "{%0,%1,%2,%3}, {%4,%5,%6,%7}, {%8,%9}, {%0,%1,%2,%3};"
                        : "+f"(c[mi][ni][0]), "+f"(c[mi][ni][1]),
                          "+f"(c[mi][ni][2]), "+f"(c[mi][ni][3])
                        : "r"(a[mi][0]), "r"(a[mi][1]), "r"(a[mi][2]), "r"(a[mi][3]),
                          "r"(b[ni][0]), "r"(b[ni][1]));
        }
    }
#undef LOAD_CHUNK

    // ---- epilogue: store xh + fused attention coefficients ----
    float as_v[4][2], ad_v[4][2];
#pragma unroll
    for (int ni = 0; ni < 4; ni++) {
        int cc = wn * 32 + ni * 8 + tg * 2;
        as_v[ni][0] = asrc[cc];     as_v[ni][1] = asrc[cc + 1];
        ad_v[ni][0] = adst[cc];     ad_v[ni][1] = adst[cc + 1];
    }

#pragma unroll
    for (int mi = 0; mi < 4; mi++) {
        int r = row0 + wm * 64 + mi * 16 + g;
        float s0 = 0.f, d0 = 0.f, s1 = 0.f, d1 = 0.f;
#pragma unroll
        for (int ni = 0; ni < 4; ni++) {
            int cc = wn * 32 + ni * 8 + tg * 2;
            if (r < N_)
                *(float2*)(g_xh + r * HID_ + cc) =
                    make_float2(c[mi][ni][0], c[mi][ni][1]);
            if (r + 8 < N_)
                *(float2*)(g_xh + (r + 8) * HID_ + cc) =
                    make_float2(c[mi][ni][2], c[mi][ni][3]);
            s0 += c[mi][ni][0] * as_v[ni][0] + c[mi][ni][1] * as_v[ni][1];
            d0 += c[mi][ni][0] * ad_v[ni][0] + c[mi][ni][1] * ad_v[ni][1];
            s1 += c[mi][ni][2] * as_v[ni][0] + c[mi][ni][3] * as_v[ni][1];
            d1 += c[mi][ni][2] * ad_v[ni][0] + c[mi][ni][3] * ad_v[ni][1];
        }
        // reduce across tg lanes (lane bits 0,1)
#pragma unroll
        for (int o = 1; o <= 2; o <<= 1) {
            s0 += __shfl_xor_sync(0xffffffffu, s0, o);
            d0 += __shfl_xor_sync(0xffffffffu, d0, o);
            s1 += __shfl_xor_sync(0xffffffffu, s1, o);
            d1 += __shfl_xor_sync(0xffffffffu, d1, o);
        }
        if (tg == 0) {
            if (r < N_)     { g_als[r * H_ + wn] = s0; g_ald[r * H_ + wn] = d0; }
            if (r + 8 < N_) { g_als[(r + 8) * H_ + wn] = s1;
                              g_ald[(r + 8) * H_ + wn] = d1; }
        }
    }
}

// ---------------- edge-attr attention scalars + g_red init -------------------
__global__ void k_wec(const float* __restrict__ We,
                      const float* __restrict__ a_edge) {
    int t = threadIdx.x;
    if (t == 0) { g_red[0] = 0.0; g_red[1] = 0.0; }
    if (t >= L_ * H_) return;
    int l = t / H_, h = t % H_;
    float s = 0.0f;
    for (int c = 0; c < C_; c++)
        s += We[l * HID_ + h * C_ + c] * a_edge[l * HID_ + h * C_ + c];
    g_wec[t] = s;
}

// ---------------- fused CSR aggregation + softmax + bias + LN-reduce ----------
// one warp per dst node; lane owns features [4*lane, 4*lane+4)
__global__ void k_agg(const float* __restrict__ bg, int l) {
    const int warp = (blockIdx.x * blockDim.x + threadIdx.x) >> 5;
    const int lane = threadIdx.x & 31;
    float s1 = 0.0f, s2 = 0.0f;

    if (warp < N_) {
        const int n  = warp;
        const int r0 = g_row[n];
        const int r1 = g_row[n + 1];
        const int h  = lane >> 3;
        const float aldh = g_ald[n * H_ + h];
        const float wech = g_wec[l * H_ + h];

        float4 acc = make_float4(0.f, 0.f, 0.f, 0.f);
        float den = 0.0f;
        int idx = r0;
        // unroll by 2: two independent gathers in flight
        for (; idx + 1 < r1; idx += 2) {
            int2 seA = g_se[idx];
            int2 seB = g_se[idx + 1];
            float lgA = g_als[seA.x * H_ + h] + aldh
                      + __int_as_float(seA.y) * wech;
            float lgB = g_als[seB.x * H_ + h] + aldh
                      + __int_as_float(seB.y) * wech;
            lgA = fmaxf(lgA, NEG_SLOPE * lgA);
            lgB = fmaxf(lgB, NEG_SLOPE * lgB);
            float exA = __expf(lgA);
            float exB = __expf(lgB);
            float4 xA = ((const float4*)g_xh)[seA.x * 32 + lane];
            float4 xB = ((const float4*)g_xh)[seB.x * 32 + lane];
            den += exA + exB;
            acc.x += exA * xA.x + exB * xB.x;
            acc.y += exA * xA.y + exB * xB.y;
            acc.z += exA * xA.z + exB * xB.z;
            acc.w += exA * xA.w + exB * xB.w;
        }
        if (idx < r1) {
            int2 se = g_se[idx];
            float lg = g_als[se.x * H_ + h] + aldh
                     + __int_as_float(se.y) * wech;
            lg = fmaxf(lg, NEG_SLOPE * lg);
            float ex = __expf(lg);
            float4 xv = ((const float4*)g_xh)[se.x * 32 + lane];
            den += ex;
            acc.x += ex * xv.x;
            acc.y += ex * xv.y;
            acc.z += ex * xv.z;
            acc.w += ex * xv.w;
        }
        float inv = 1.0f / (den + 1e-16f);
        float4 b4 = ((const float4*)bg)[lane];
        float4 o;
        o.x = acc.x * inv + b4.x;
        o.y = acc.y * inv + b4.y;
        o.z = acc.z * inv + b4.z;
        o.w = acc.w * inv + b4.w;
        ((float4*)g_g)[n * 32 + lane] = o;
        s1 = o.x + o.y + o.z + o.w;
        s2 = o.x * o.x + o.y * o.y + o.z * o.z + o.w * o.w;
    }

#pragma unroll
    for (int o = 16; o > 0; o >>= 1) {
        s1 += __shfl_xor_sync(0xffffffffu, s1, o);
        s2 += __shfl_xor_sync(0xffffffffu, s2, o);
    }
    __shared__ float r1[8], r2[8];
    int wl = threadIdx.x >> 5;
    if (lane == 0) { r1[wl] = s1; r2[wl] = s2; }
    __syncthreads();
    if (threadIdx.x < 8) {
        float a = r1[threadIdx.x], b = r2[threadIdx.x];
#pragma unroll
        for (int o = 4; o > 0; o >>= 1) {
            a += __shfl_xor_sync(0xffu, a, o);
            b += __shfl_xor_sync(0xffu, b, o);
        }
        if (threadIdx.x == 0) {
            atomicAdd(&g_red[0], (double)a);
            atomicAdd(&g_red[1], (double)b);
        }
    }
}

// compute stats, then reset g_red for next layer
__global__ void k_stats() {
    double M = (double)N_ * (double)HID_;
    double mean = g_red[0] / M;
    double var  = g_red[1] / M - mean * mean;
    g_stats[0] = (float)mean;
    g_stats[1] = (float)(1.0 / sqrt(var + 1e-5));
    g_red[0] = 0.0;
    g_red[1] = 0.0;
}

// ---------------- output projection with fused final apply --------------------
__global__ void k_out(const float* __restrict__ Wout,
                      const float* __restrict__ bout,
                      const float* __restrict__ lnw,
                      const float* __restrict__ lnb,
                      float* __restrict__ out) {
    __shared__ float ws[HID_ * OUT_];
    __shared__ float bs[OUT_];
    __shared__ float lw[HID_], lb[HID_];
    for (int i = threadIdx.x; i < HID_ * OUT_; i += blockDim.x) ws[i] = Wout[i];
    for (int i = threadIdx.x; i < HID_; i += blockDim.x) {
        lw[i] = lnw[i]; lb[i] = lnb[i];
    }
    if (threadIdx.x < OUT_) bs[threadIdx.x] = bout[threadIdx.x];
    __syncthreads();
    int n = blockIdx.x * blockDim.x + threadIdx.x;
    if (n >= N_) return;
    const float mean = g_stats[0], istd = g_stats[1];
    float acc[OUT_];
#pragma unroll
    for (int j = 0; j < OUT_; j++) acc[j] = bs[j];
    const float4* gr = (const float4*)(g_g + n * HID_);
    const float4* hr = (const float4*)(g_h + n * HID_);
#pragma unroll 8
    for (int k4 = 0; k4 < 32; k4++) {
        float4 gv = gr[k4];
        float4 hv = hr[k4];
        float hvv[4];
        hvv[0] = fmaxf((gv.x - mean) * istd * lw[k4 * 4 + 0] + lb[k4 * 4 + 0] + hv.x, 0.f);
        hvv[1] = fmaxf((gv.y - mean) * istd * lw[k4 * 4 + 1] + lb[k4 * 4 + 1] + hv.y, 0.f);
        hvv[2] = fmaxf((gv.z - mean) * istd * lw[k4 * 4 + 2] + lb[k4 * 4 + 2] + hv.z, 0.f);
        hvv[3] = fmaxf((gv.w - mean) * istd * lw[k4 * 4 + 3] + lb[k4 * 4 + 3] + hv.w, 0.f);
#pragma unroll
        for (int tt = 0; tt < 4; tt++) {
            int k = k4 * 4 + tt;
#pragma unroll
            for (int j = 0; j < OUT_; j++) acc[j] += hvv[tt] * ws[k * OUT_ + j];
        }
    }
#pragma unroll
    for (int j = 0; j < OUT_; j++) out[n * OUT_ + j] = acc[j];
}

// ---------------- launch ------------------------------------------------------
extern "C" void kernel_launch(void* const* d_in, const int* in_sizes, int n_in,
                              void* d_out, int out_size) {
    const float* x      = (const float*)d_in[0];
    const int*   ei     = (const int*)d_in[1];   // int32 (JAX x64 disabled)
    const float* ea     = (const float*)d_in[2];
    const float* Win    = (const float*)d_in[3];
    const float* b_in   = (const float*)d_in[4];
    const float* Wg     = (const float*)d_in[5];
    const float* bg     = (const float*)d_in[6];
    const float* a_src  = (const float*)d_in[7];
    const float* a_dst  = (const float*)d_in[8];
    const float* We     = (const float*)d_in[9];
    const float* a_edge = (const float*)d_in[10];
    const float* ln_w   = (const float*)d_in[11];
    const float* ln_b   = (const float*)d_in[12];
    const float* Wout   = (const float*)d_in[13];
    const float* bout   = (const float*)d_in[14];
    float*       out    = (float*)d_out;

    // CSR build (dst-sorted, self loops first per node)
    k_cnt_init     <<<(N_ + 255) / 256, 256>>>();
    k_hist         <<<(E_ + 255) / 256, 256>>>(ei, ea);
    k_scan1        <<<NBSCAN, 1024>>>();
    k_scan2        <<<1, 128>>>();
    k_node_fin     <<<(N_ + 255) / 256, 256>>>();
    k_scatter_edges<<<(E_ + 255) / 256, 256>>>(ei, ea);

    k_ingemm<<<(N_ + 63) / 64, 256>>>(x, Win, b_in);
    k_wec   <<<1, 32>>>(We, a_edge);

    for (int l = 0; l < L_; l++) {
        k_gemm_tc<<<GBLK, 256>>>(Wg + l * HID_ * HID_,
                                 a_src + l * H_ * C_, a_dst + l * H_ * C_,
                                 l > 0 ? (ln_w + (l - 1) * HID_) : ln_w,
                                 l > 0 ? (ln_b + (l - 1) * HID_) : ln_b,
                                 l > 0 ? 1 : 0);
        k_agg  <<<(N_ + 7) / 8, 256>>>(bg + l * HID_, l);
        k_stats<<<1, 1>>>();
    }
    k_out<<<(N_ + 255) / 256, 256>>>(Wout, bout,
                                     ln_w + (L_ - 1) * HID_,
                                     ln_b + (L_ - 1) * HID_, out);
}